// round 14
// baseline (speedup 1.0000x reference)
#include <cuda_runtime.h>

#define N_NODES 20000
#define N_EDGES 640000
#define D 128
#define NBLK 148
#define NTHR 1024
#define GEMM_TICKETS 5000   // 4 rows per warp-ticket
#define GATH_TICKETS 5000   // 4 nodes per warp-ticket

// ---- scratch (no allocations). .bss zero-init; deterministic for replays. ----
__device__ int      g_deg[N_NODES];
__device__ int      g_cursor[N_NODES];
__device__ int      g_rowstart[N_NODES + 1];
__device__ int      g_csr[N_EDGES];
__device__ float    g_z [N_NODES * D];   // Z = h@W scratch
__device__ float    g_hA[N_NODES * D];
__device__ float    g_hB[N_NODES * D];
__device__ unsigned g_bar_count;
__device__ unsigned g_bar_sense;
__device__ int      g_ctr[8];            // 4 gemm + 4 gather ticket counters

typedef unsigned long long ull;

struct SMem {
    float Xs[32][4][128];  // 64 KB : per-warp 4-row staging for GEMM phase
    float Wf[128][128];    // 64 KB : full W, block-shared per layer
};

// ---- packed f32x2 helpers ----
__device__ __forceinline__ ull f2_pack(float x) {
    ull r; asm("mov.b64 %0,{%1,%1};" : "=l"(r) : "f"(x)); return r;
}
__device__ __forceinline__ ull f2_add(ull a, ull b) {
    ull d; asm("add.rn.f32x2 %0,%1,%2;" : "=l"(d) : "l"(a), "l"(b)); return d;
}
__device__ __forceinline__ ull f2_fma(ull a, ull b, ull c) {
    ull d; asm("fma.rn.f32x2 %0,%1,%2,%3;" : "=l"(d) : "l"(a), "l"(b), "l"(c)); return d;
}

// sense-reversing grid barrier; all NBLK blocks co-resident (1/SM).
__device__ __forceinline__ void grid_barrier(unsigned& sense, int* reset_ctr) {
    __syncthreads();
    sense ^= 1u;
    if (threadIdx.x == 0) {
        __threadfence();
        unsigned arrived = atomicAdd(&g_bar_count, 1u);
        if (arrived == NBLK - 1) {
            g_bar_count = 0;
            if (reset_ctr) *reset_ctr = 0;
            __threadfence();
            atomicExch(&g_bar_sense, sense);
        } else {
            while (atomicAdd(&g_bar_sense, 0u) != sense) __nanosleep(64);
        }
    }
    __syncthreads();
}

// ---------------------------------------------------------------------------
// GEMM phase: zout[0:N, :] = hin @ W   (no bias; bias added in gather phase)
// Warp-ticket = 4 rows: gmem->smem stage, then R11-style packed GEMM.
__device__ __forceinline__ void gemm_phase(
    SMem& sm,
    const float* __restrict__ hin,
    const float* __restrict__ W,
    float* __restrict__ zout,
    int* ctr)
{
    const int tid  = threadIdx.x;
    const int lane = tid & 31;
    const int wid  = tid >> 5;
    const float4* __restrict__ hv = (const float4*)hin;

    // load full W into smem (4096 float4 / 1024 threads = 4 each)
#pragma unroll
    for (int i = 0; i < 4; i++) {
        int idx = tid + i * NTHR;
        int k   = idx >> 5;
        int c4  = (idx & 31) * 4;
        *(float4*)&sm.Wf[k][c4] = __ldg((const float4*)&W[k * 128 + c4]);
    }
    __syncthreads();

    float (*Xw)[128] = sm.Xs[wid];
    const int cb = lane * 4;

    for (;;) {
        int t;
        if (lane == 0) t = atomicAdd(ctr, 1);
        t = __shfl_sync(0xffffffffu, t, 0);
        if (t >= GEMM_TICKETS) break;
        const int node0 = t * 4;

        // stage 4 input rows gmem -> smem (1 LDG.128 + 1 STS.128 per row)
#pragma unroll
        for (int r = 0; r < 4; r++)
            *(float4*)&Xw[r][lane * 4] = hv[(node0 + r) * 32 + lane];
        __syncwarp();

        ull A[4][2];
#pragma unroll
        for (int r = 0; r < 4; r++) { A[r][0] = 0ull; A[r][1] = 0ull; }

#pragma unroll 2
        for (int k = 0; k < 128; k += 4) {
            float4 xf[4];
#pragma unroll
            for (int r = 0; r < 4; r++)
                xf[r] = *(const float4*)&Xw[r][k];     // warp-broadcast LDS.128
#pragma unroll
            for (int kk = 0; kk < 4; kk++) {
                ulonglong2 w2 = *(const ulonglong2*)&sm.Wf[k + kk][cb];
#pragma unroll
                for (int r = 0; r < 4; r++) {
                    float xv = (kk == 0) ? xf[r].x : (kk == 1) ? xf[r].y
                             : (kk == 2) ? xf[r].z : xf[r].w;
                    ull xp = f2_pack(xv);
                    A[r][0] = f2_fma(xp, w2.x, A[r][0]);
                    A[r][1] = f2_fma(xp, w2.y, A[r][1]);
                }
            }
        }

#pragma unroll
        for (int r = 0; r < 4; r++) {
            ulonglong2 o; o.x = A[r][0]; o.y = A[r][1];
            *(ulonglong2*)&zout[(long)(node0 + r) * D + cb] = o;
        }
        __syncwarp();
    }
}

// ---------------------------------------------------------------------------
// Gather phase: hout[i,:] = z[i,:] + bias + sum_{j in nbrs(i)} z[j,:]
// Pure memory phase: no smem, no __syncthreads; 8-deep staged unpredicated
// loads keep 8 LDG.128 in flight per warp at all times.
__device__ __forceinline__ void gather_phase(
    const float* __restrict__ z,
    const float* __restrict__ bias,
    float* __restrict__ hout,
    int* ctr)
{
    const int lane = threadIdx.x & 31;
    const ulonglong2* __restrict__ zv = (const ulonglong2*)z;
    const int cb = lane * 4;
    const ulonglong2 bv = *(const ulonglong2*)&bias[cb];

    for (;;) {
        int t;
        if (lane == 0) t = atomicAdd(ctr, 1);
        t = __shfl_sync(0xffffffffu, t, 0);
        if (t >= GATH_TICKETS) break;
        const int node0 = t * 4;

#pragma unroll
        for (int n = 0; n < 4; n++) {
            const int node = node0 + n;
            ulonglong2 s = zv[node * 32 + lane];
            ull a0 = f2_add(s.x, bv.x), a1 = f2_add(s.y, bv.y);
            ull b0 = 0ull, b1 = 0ull;
            const int beg = g_rowstart[node];
            const int end = g_rowstart[node + 1];
            const int mainend = beg + ((end - beg) & ~7);
            int k = beg;
            for (; k < mainend; k += 8) {
                int myj = g_csr[k + (lane & 7)];
                int j0 = __shfl_sync(0xffffffffu, myj, 0);
                int j1 = __shfl_sync(0xffffffffu, myj, 1);
                int j2 = __shfl_sync(0xffffffffu, myj, 2);
                int j3 = __shfl_sync(0xffffffffu, myj, 3);
                int j4 = __shfl_sync(0xffffffffu, myj, 4);
                int j5 = __shfl_sync(0xffffffffu, myj, 5);
                int j6 = __shfl_sync(0xffffffffu, myj, 6);
                int j7 = __shfl_sync(0xffffffffu, myj, 7);
                ulonglong2 v0 = zv[j0 * 32 + lane];
                ulonglong2 v1 = zv[j1 * 32 + lane];
                ulonglong2 v2 = zv[j2 * 32 + lane];
                ulonglong2 v3 = zv[j3 * 32 + lane];
                ulonglong2 v4 = zv[j4 * 32 + lane];
                ulonglong2 v5 = zv[j5 * 32 + lane];
                ulonglong2 v6 = zv[j6 * 32 + lane];
                ulonglong2 v7 = zv[j7 * 32 + lane];
                a0 = f2_add(a0, v0.x); a1 = f2_add(a1, v0.y);
                b0 = f2_add(b0, v1.x); b1 = f2_add(b1, v1.y);
                a0 = f2_add(a0, v2.x); a1 = f2_add(a1, v2.y);
                b0 = f2_add(b0, v3.x); b1 = f2_add(b1, v3.y);
                a0 = f2_add(a0, v4.x); a1 = f2_add(a1, v4.y);
                b0 = f2_add(b0, v5.x); b1 = f2_add(b1, v5.y);
                a0 = f2_add(a0, v6.x); a1 = f2_add(a1, v6.y);
                b0 = f2_add(b0, v7.x); b1 = f2_add(b1, v7.y);
            }
            if (k < end) {
                int kk  = k + (lane & 7);
                int myj = (kk < end) ? g_csr[kk] : -1;
#pragma unroll
                for (int e = 0; e < 8; e++) {
                    int j = __shfl_sync(0xffffffffu, myj, e);
                    if (j >= 0) {
                        ulonglong2 v = zv[j * 32 + lane];
                        a0 = f2_add(a0, v.x);
                        a1 = f2_add(a1, v.y);
                    }
                }
            }
            a0 = f2_add(a0, b0);
            a1 = f2_add(a1, b1);
            ulonglong2 o; o.x = a0; o.y = a1;
            *(ulonglong2*)&hout[(long)node * D + cb] = o;
        }
    }
}

// ---------------------------------------------------------------------------
__global__ __launch_bounds__(NTHR) void gin_persistent_kernel(
    const float* __restrict__ h,
    const int*   __restrict__ ei,
    const float* __restrict__ W0, const float* __restrict__ b0,
    const float* __restrict__ W1, const float* __restrict__ b1,
    const float* __restrict__ W2, const float* __restrict__ b2,
    const float* __restrict__ W3, const float* __restrict__ b3,
    float* __restrict__ out)
{
    extern __shared__ char smem_raw[];
    SMem& sm = *reinterpret_cast<SMem*>(smem_raw);
    const int tid = threadIdx.x;

    unsigned sense = *(volatile unsigned*)&g_bar_sense;   // parity-agnostic

    // ---- Phase 1: count in-degrees, THEN (same phase) GEMM0: g_z = h@W0.
    // GEMM0 needs no graph info, so it overlaps the CSR pipeline for free.
    for (int e = blockIdx.x * NTHR + tid; e < N_EDGES; e += NBLK * NTHR)
        atomicAdd(&g_deg[ei[N_EDGES + e]], 1);
    gemm_phase(sm, h, W0, g_z, &g_ctr[0]);
    grid_barrier(sense, &g_ctr[0]);

    // ---- Phase 2: exclusive scan (block 0), reset deg/cursor ----
    if (blockIdx.x == 0) {
        int* partial = (int*)sm.Xs;
        const int CH = (N_NODES + NTHR - 1) / NTHR;        // 20
        const int base = tid * CH;

        int s = 0;
        for (int j = 0; j < CH; j++) {
            int idx = base + j;
            if (idx < N_NODES) s += g_deg[idx];
        }
        partial[tid] = s;
        __syncthreads();
        for (int off = 1; off < NTHR; off <<= 1) {
            int v = 0;
            if (tid >= off) v = partial[tid - off];
            __syncthreads();
            if (tid >= off) partial[tid] += v;
            __syncthreads();
        }
        int run = (tid > 0) ? partial[tid - 1] : 0;
        for (int j = 0; j < CH; j++) {
            int idx = base + j;
            if (idx < N_NODES) {
                g_rowstart[idx] = run;
                run += g_deg[idx];
                g_deg[idx]    = 0;
                g_cursor[idx] = 0;
            }
        }
        if (tid == NTHR - 1) g_rowstart[N_NODES] = partial[NTHR - 1];
        __syncthreads();
    }
    grid_barrier(sense, nullptr);

    // ---- Phase 3: fill CSR ----
    for (int e = blockIdx.x * NTHR + tid; e < N_EDGES; e += NBLK * NTHR) {
        int s = ei[e];
        int d = ei[N_EDGES + e];
        int pos = atomicAdd(&g_cursor[d], 1);
        g_csr[g_rowstart[d] + pos] = s;
    }
    grid_barrier(sense, nullptr);

    // ---- Layers: gather_l then GEMM_{l+1}, alternating ----
    gather_phase(g_z, b0, g_hA, &g_ctr[1]);        // h1 = Z0 + A Z0 + b0
    grid_barrier(sense, &g_ctr[1]);
    gemm_phase(sm, g_hA, W1, g_z, &g_ctr[2]);      // Z1 = h1 @ W1
    grid_barrier(sense, &g_ctr[2]);
    gather_phase(g_z, b1, g_hB, &g_ctr[3]);        // h2
    grid_barrier(sense, &g_ctr[3]);
    gemm_phase(sm, g_hB, W2, g_z, &g_ctr[4]);      // Z2
    grid_barrier(sense, &g_ctr[4]);
    gather_phase(g_z, b2, g_hA, &g_ctr[5]);        // h3
    grid_barrier(sense, &g_ctr[5]);
    gemm_phase(sm, g_hA, W3, g_z, &g_ctr[6]);      // Z3
    grid_barrier(sense, &g_ctr[6]);
    gather_phase(g_z, b3, out, &g_ctr[7]);         // out = Z3 + A Z3 + b3
    grid_barrier(sense, &g_ctr[7]);                // resets last counter
}

// ---------------------------------------------------------------------------
extern "C" void kernel_launch(void* const* d_in, const int* in_sizes, int n_in,
                              void* d_out, int out_size) {
    const float* h  = (const float*)d_in[0];
    const int*   ei = (const int*)d_in[1];

    cudaFuncSetAttribute(gin_persistent_kernel,
                         cudaFuncAttributeMaxDynamicSharedMemorySize,
                         (int)sizeof(SMem));

    gin_persistent_kernel<<<NBLK, NTHR, sizeof(SMem)>>>(
        h, ei,
        (const float*)d_in[2], (const float*)d_in[3],
        (const float*)d_in[4], (const float*)d_in[5],
        (const float*)d_in[6], (const float*)d_in[7],
        (const float*)d_in[8], (const float*)d_in[9],
        (float*)d_out);
}

// round 15
// speedup vs baseline: 1.4243x; 1.4243x over previous
#include <cuda_runtime.h>

#define N_NODES 20000
#define N_EDGES 640000
#define D 128
#define NBLK 148
#define NTHR 1024
#define WTICKETS 5000     // 4 nodes per warp-ticket; 5000*4 == N_NODES exactly
#define CAP 128           // adjacency bucket capacity per node (P(overflow)~0)

// ---- scratch (no allocations). .bss zero-init. g_cnt is reset by the last
// gather each run; counters reset at barriers -> graph replays deterministic. ----
__device__ int      g_cnt[N_NODES];          // in-degree / bucket cursor
__device__ int      g_adj[N_NODES * CAP];    // bucketed adjacency (src lists)
__device__ float    g_h0[N_NODES * D];
__device__ float    g_h1[N_NODES * D];
__device__ float    g_h2[N_NODES * D];
__device__ unsigned g_bar_count;
__device__ unsigned g_bar_sense;
__device__ int      g_tile_ctr[4];

typedef unsigned long long ull;

struct SMem {
    float Xs[32][4][128];  // 64 KB : per-warp private 4-row staging
    float Wf[128][128];    // 64 KB : full W, block-shared per layer
};

// ---- packed f32x2 helpers ----
__device__ __forceinline__ ull f2_pack(float x) {
    ull r; asm("mov.b64 %0,{%1,%1};" : "=l"(r) : "f"(x)); return r;
}
__device__ __forceinline__ ull f2_add(ull a, ull b) {
    ull d; asm("add.rn.f32x2 %0,%1,%2;" : "=l"(d) : "l"(a), "l"(b)); return d;
}
__device__ __forceinline__ ull f2_fma(ull a, ull b, ull c) {
    ull d; asm("fma.rn.f32x2 %0,%1,%2,%3;" : "=l"(d) : "l"(a), "l"(b), "l"(c)); return d;
}

// sense-reversing grid barrier; all NBLK blocks co-resident (1/SM).
__device__ __forceinline__ void grid_barrier(unsigned& sense, int* reset_ctr) {
    __syncthreads();
    sense ^= 1u;
    if (threadIdx.x == 0) {
        __threadfence();
        unsigned arrived = atomicAdd(&g_bar_count, 1u);
        if (arrived == NBLK - 1) {
            g_bar_count = 0;
            if (reset_ctr) *reset_ctr = 0;
            __threadfence();
            atomicExch(&g_bar_sense, sense);
        } else {
            while (atomicAdd(&g_bar_sense, 0u) != sense) __nanosleep(64);
        }
    }
    __syncthreads();
}

// ---------------------------------------------------------------------------
// one fused layer, warp-autonomous (R11 champion structure, bucket adjacency).
// If reset_cnt != 0 (last layer), zero g_cnt[node] after the output write so
// the next replay starts from a clean cursor array.
__device__ __forceinline__ void do_layer(
    SMem& sm,
    const float* __restrict__ hin,
    const float* __restrict__ W,
    const float* __restrict__ bias,
    float* __restrict__ hout,
    int* ticket_ctr,
    int reset_cnt)
{
    const int tid  = threadIdx.x;
    const int lane = tid & 31;
    const int wid  = tid >> 5;
    const float4* __restrict__ hv = (const float4*)hin;

    // ---- load full W into smem (4096 float4 / 1024 threads = 4 each) ----
#pragma unroll
    for (int i = 0; i < 4; i++) {
        int idx = tid + i * NTHR;
        int k   = idx >> 5;
        int c4  = (idx & 31) * 4;
        *(float4*)&sm.Wf[k][c4] = __ldg((const float4*)&W[k * 128 + c4]);
    }
    __syncthreads();

    float (*Xw)[128] = sm.Xs[wid];
    const int cb = lane * 4;
    const ulonglong2 bv = *(const ulonglong2*)&bias[cb];

    for (;;) {
        int t;
        if (lane == 0) t = atomicAdd(ticket_ctr, 1);
        t = __shfl_sync(0xffffffffu, t, 0);
        if (t >= WTICKETS) break;
        const int node0 = t * 4;

        // ---- gather 4 node rows (16 edges in flight per warp) ----
#pragma unroll
        for (int n = 0; n < 4; n++) {
            int node = node0 + n;
            float4 a = hv[node * 32 + lane];
            const int beg = node * CAP;
            const int end = beg + g_cnt[node];
            for (int k = beg; k < end; k += 16) {
                int kk = k + (lane & 15);
                int myj = (kk < end) ? g_adj[kk] : -1;
#pragma unroll
                for (int e = 0; e < 16; e++) {
                    int j = __shfl_sync(0xffffffffu, myj, e);
                    if (j >= 0) {
                        float4 v = hv[j * 32 + lane];
                        a.x += v.x; a.y += v.y; a.z += v.z; a.w += v.w;
                    }
                }
            }
            *(float4*)&Xw[n][lane * 4] = a;
        }
        __syncwarp();

        // ---- GEMM: hout[node0:node0+4, cb:cb+4] = Xw @ Wf + b ----
        ull A[4][2];
#pragma unroll
        for (int r = 0; r < 4; r++) { A[r][0] = 0ull; A[r][1] = 0ull; }

#pragma unroll 2
        for (int k = 0; k < 128; k += 4) {
            float4 xf[4];
#pragma unroll
            for (int r = 0; r < 4; r++)
                xf[r] = *(const float4*)&Xw[r][k];     // warp-broadcast
#pragma unroll
            for (int kk = 0; kk < 4; kk++) {
                ulonglong2 w2 = *(const ulonglong2*)&sm.Wf[k + kk][cb];
#pragma unroll
                for (int r = 0; r < 4; r++) {
                    float xv = (kk == 0) ? xf[r].x : (kk == 1) ? xf[r].y
                             : (kk == 2) ? xf[r].z : xf[r].w;
                    ull xp = f2_pack(xv);
                    A[r][0] = f2_fma(xp, w2.x, A[r][0]);
                    A[r][1] = f2_fma(xp, w2.y, A[r][1]);
                }
            }
        }

#pragma unroll
        for (int r = 0; r < 4; r++) {
            ulonglong2 o;
            o.x = f2_add(A[r][0], bv.x);
            o.y = f2_add(A[r][1], bv.y);
            *(ulonglong2*)&hout[(long)(node0 + r) * D + cb] = o;
        }
        if (reset_cnt && lane < 4) g_cnt[node0 + lane] = 0;  // replay hygiene
        __syncwarp();   // Xw reads done before next ticket's gather writes
    }
}

// ---------------------------------------------------------------------------
__global__ __launch_bounds__(NTHR) void gin_persistent_kernel(
    const float* __restrict__ h,
    const int*   __restrict__ ei,
    const float* __restrict__ W0, const float* __restrict__ b0,
    const float* __restrict__ W1, const float* __restrict__ b1,
    const float* __restrict__ W2, const float* __restrict__ b2,
    const float* __restrict__ W3, const float* __restrict__ b3,
    float* __restrict__ out)
{
    extern __shared__ char smem_raw[];
    SMem& sm = *reinterpret_cast<SMem*>(smem_raw);
    const int tid = threadIdx.x;

    unsigned sense = *(volatile unsigned*)&g_bar_sense;   // parity-agnostic

    // ---- Phase 1: ONE-PASS bucketed adjacency fill (g_cnt is 0 on entry:
    // .bss zero on first run, reset by last layer's gather on later runs) ----
    for (int e = blockIdx.x * NTHR + tid; e < N_EDGES; e += NBLK * NTHR) {
        int s = ei[e];
        int d = ei[N_EDGES + e];
        int pos = atomicAdd(&g_cnt[d], 1);
        g_adj[d * CAP + pos] = s;
    }
    grid_barrier(sense, nullptr);

    // ---- Phases 2-5: the four GIN layers (warp-level dynamic tickets) ----
    do_layer(sm, h,    W0, b0, g_h0, &g_tile_ctr[0], 0);
    grid_barrier(sense, &g_tile_ctr[0]);
    do_layer(sm, g_h0, W1, b1, g_h1, &g_tile_ctr[1], 0);
    grid_barrier(sense, &g_tile_ctr[1]);
    do_layer(sm, g_h1, W2, b2, g_h2, &g_tile_ctr[2], 0);
    grid_barrier(sense, &g_tile_ctr[2]);
    do_layer(sm, g_h2, W3, b3, out,  &g_tile_ctr[3], 1);   // resets g_cnt
    grid_barrier(sense, &g_tile_ctr[3]);                   // resets last ctr
}

// ---------------------------------------------------------------------------
extern "C" void kernel_launch(void* const* d_in, const int* in_sizes, int n_in,
                              void* d_out, int out_size) {
    const float* h  = (const float*)d_in[0];
    const int*   ei = (const int*)d_in[1];

    cudaFuncSetAttribute(gin_persistent_kernel,
                         cudaFuncAttributeMaxDynamicSharedMemorySize,
                         (int)sizeof(SMem));

    gin_persistent_kernel<<<NBLK, NTHR, sizeof(SMem)>>>(
        h, ei,
        (const float*)d_in[2], (const float*)d_in[3],
        (const float*)d_in[4], (const float*)d_in[5],
        (const float*)d_in[6], (const float*)d_in[7],
        (const float*)d_in[8], (const float*)d_in[9],
        (float*)d_out);
}